// round 15
// baseline (speedup 1.0000x reference)
#include <cuda_runtime.h>
#include <cuda_bf16.h>
#include <cstdint>

#define B_SZ 256
#define ED   128
#define HID  256
#define FEAT 2688
#define NENT 40943
#define W2COLS 344064   // FEAT*ED
#define NJC  84         // 84 * 32 = 2688 j-chunks
#define NPLANE (NJC * 2)   // j-chunk x h-half partial planes

__device__ float d_E1[B_SZ * ED];
__device__ float d_R[B_SZ * ED];
__device__ float d_stats[2];
__device__ float d_H[4 * B_SZ * HID];      // planes: Hc, Hcb, Hf, Hfb
__device__ float d_filt[B_SZ * 288];
__device__ float d_cbias[B_SZ * 32];
__device__ float d_fcb[B_SZ * ED];
__device__ float d_X[B_SZ * FEAT];
__device__ float d_X2p[NPLANE * B_SZ * ED]; // split (j,h) partials
__device__ float d_X2[B_SZ * ED];
__device__ float d_Xbn[B_SZ * ED];
// W2 pre-packed to bf16 pairs: P[h2][col] = bf2(W2[2h2][col], W2[2h2+1][col])
__device__ uint32_t d_W2bf[128 * W2COLS];  // 176 MB

__device__ __forceinline__ uint32_t pack_bf2(float lo, float hi) {
    __nv_bfloat162 b = __floats2bfloat162_rn(lo, hi);
    return *reinterpret_cast<uint32_t*>(&b);
}
__device__ __forceinline__ float tf32r(float x) {
    unsigned u; asm("cvt.rna.tf32.f32 %0, %1;" : "=r"(u) : "f"(x));
    return __uint_as_float(u);
}
__device__ __forceinline__ uint32_t smem_u32(const void* p) {
    return (uint32_t)__cvta_generic_to_shared(p);
}
#define CP16(d, s) asm volatile("cp.async.cg.shared.global [%0], [%1], 16;" :: "r"(d), "l"(s))
#define CP_COMMIT() asm volatile("cp.async.commit_group;")
#define CP_WAIT2()  asm volatile("cp.async.wait_group 2;")

__global__ void k_gather(const int* __restrict__ e1, const int* __restrict__ r,
                         const float* __restrict__ ent, const float* __restrict__ rel) {
    int idx = blockIdx.x * 256 + threadIdx.x;
    int i = idx >> 7, c = idx & 127;
    d_E1[idx] = ent[(size_t)e1[i] * ED + c];
    d_R[idx]  = rel[(size_t)r[i]  * ED + c];
}

__global__ void k_w2cast(const float* __restrict__ W2) {
    int h2 = blockIdx.y;
    int col = blockIdx.x * 1024 + threadIdx.x * 4;
    const float4 lo = *(const float4*)(W2 + (size_t)(2 * h2) * W2COLS + col);
    const float4 hi = *(const float4*)(W2 + (size_t)(2 * h2 + 1) * W2COLS + col);
    uint4 w = make_uint4(pack_bf2(lo.x, hi.x), pack_bf2(lo.y, hi.y),
                         pack_bf2(lo.z, hi.z), pack_bf2(lo.w, hi.w));
    *(uint4*)&d_W2bf[(size_t)h2 * W2COLS + col] = w;
}

__global__ void k_bn0() {
    __shared__ float rs[8], rss[8];
    int tid = threadIdx.x;
    float s = 0.f, ss = 0.f;
    for (int idx = tid; idx < B_SZ * ED; idx += 256) {
        float v = d_E1[idx]; s += v; ss += v * v;
    }
    for (int o = 16; o; o >>= 1) {
        s  += __shfl_xor_sync(0xffffffffu, s,  o);
        ss += __shfl_xor_sync(0xffffffffu, ss, o);
    }
    if ((tid & 31) == 0) { rs[tid >> 5] = s; rss[tid >> 5] = ss; }
    __syncthreads();
    if (tid == 0) {
        float S = 0.f, SS = 0.f;
        for (int w = 0; w < 8; ++w) { S += rs[w]; SS += rss[w]; }
        const float inv = 1.0f / (B_SZ * ED);
        float m = S * inv, var = SS * inv - m * m;
        d_stats[0] = m; d_stats[1] = rsqrtf(var + 1e-5f);
    }
}

__device__ __forceinline__ void gemm64_body(const float* __restrict__ A,
                                            const float* __restrict__ Bw,
                                            float* __restrict__ C,
                                            int K, int N, int doRelu,
                                            int i0, int n0) {
    __shared__ float sA[16 * 64];
    __shared__ float sB[16 * 64];
    const int tid = threadIdx.x;
    const int ty = tid >> 4, tx = tid & 15;
    float acc[4][4] = {};
    for (int kb = 0; kb < K; kb += 16) {
        #pragma unroll
        for (int t = 0; t < 4; ++t) {
            int idx = tid + t * 256;
            int kk = idx & 15, ii = idx >> 4;
            sA[kk * 64 + ii] = A[(i0 + ii) * K + kb + kk];
            int nn = idx & 63, kk2 = idx >> 6;
            int n = n0 + nn;
            sB[kk2 * 64 + nn] = (n < N) ? Bw[(size_t)(kb + kk2) * N + n] : 0.f;
        }
        __syncthreads();
        #pragma unroll
        for (int kk = 0; kk < 16; ++kk) {
            float a[4], b[4];
            #pragma unroll
            for (int u = 0; u < 4; ++u) a[u] = sA[kk * 64 + ty * 4 + u];
            #pragma unroll
            for (int v = 0; v < 4; ++v) b[v] = sB[kk * 64 + tx * 4 + v];
            #pragma unroll
            for (int u = 0; u < 4; ++u)
                #pragma unroll
                for (int v = 0; v < 4; ++v)
                    acc[u][v] = fmaf(a[u], b[v], acc[u][v]);
        }
        __syncthreads();
    }
    #pragma unroll
    for (int u = 0; u < 4; ++u) {
        int row = i0 + ty * 4 + u;
        #pragma unroll
        for (int v = 0; v < 4; ++v) {
            int col = n0 + tx * 4 + v;
            if (col < N) {
                float val = acc[u][v];
                if (doRelu) val = fmaxf(val, 0.f);
                C[(size_t)row * N + col] = val;
            }
        }
    }
}

__global__ void k_cpg1(const float* __restrict__ w0, const float* __restrict__ w1,
                       const float* __restrict__ w2, const float* __restrict__ w3) {
    const float* Bw = (blockIdx.z == 0) ? w0 : (blockIdx.z == 1) ? w1
                    : (blockIdx.z == 2) ? w2 : w3;
    float* C = d_H + (size_t)blockIdx.z * (B_SZ * HID);
    gemm64_body(d_R, Bw, C, 128, 256, 1, blockIdx.y * 64, blockIdx.x * 64);
}

__global__ void k_cpg2(const float* __restrict__ convw_w2,
                       const float* __restrict__ convb_w2,
                       const float* __restrict__ fcb_w2) {
    int z = blockIdx.z;
    const float* A; const float* Bw; float* C; int N;
    if (z == 0)      { A = d_H;                  Bw = convw_w2; C = d_filt;  N = 288; }
    else if (z == 1) { A = d_H + B_SZ * HID;     Bw = convb_w2; C = d_cbias; N = 32;  }
    else             { A = d_H + 3 * B_SZ * HID; Bw = fcb_w2;   C = d_fcb;   N = 128; }
    int n0 = blockIdx.x * 64;
    if (n0 >= N) return;
    gemm64_body(A, Bw, C, 256, N, 0, blockIdx.y * 64, n0);
}

__global__ void k_conv() {
    __shared__ float sx[128];
    __shared__ float sf[288];
    __shared__ float scb[32];
    const int i = blockIdx.x, tid = threadIdx.x;
    const float mean = d_stats[0], istd = d_stats[1];
    if (tid < 128) sx[tid] = (d_E1[i * 128 + tid] - mean) * istd;
    if (tid < 32)  scb[tid] = d_cbias[i * 32 + tid];
    for (int q = tid; q < 288; q += 256) sf[q] = d_filt[i * 288 + q];
    __syncthreads();
    for (int oi = tid; oi < FEAT; oi += 256) {
        int c = oi / 84, rem = oi - c * 84;
        int y = rem / 14, x = rem - y * 14;
        float a = scb[c];
        #pragma unroll
        for (int ky = 0; ky < 3; ++ky)
            #pragma unroll
            for (int kx = 0; kx < 3; ++kx)
                a = fmaf(sx[(y + ky) * 16 + (x + kx)], sf[c * 9 + ky * 3 + kx], a);
        d_X[i * FEAT + oi] = fmaxf(a, 0.f);
    }
}

// ---------- dominant contraction: bf16 mma m16n8k16, cp.async ring, h-split ------
__global__ void __launch_bounds__(256, 2) k_bigfused() {
    extern __shared__ uint32_t smw[];
    uint32_t* sApk = smw;                    // [h2=64][72]
    uint32_t* sBpk = smw + 4608;             // 4 x [k2=16][136]
    float*    sX   = (float*)(smw + 4608 + 8704);   // [jj=32][72]
    const int tid = threadIdx.x;
    const int lane = tid & 31, wid = tid >> 5;
    const int g = lane >> 2, c = lane & 3;
    const int iw0 = (wid & 3) * 16;
    const int kw0 = (wid >> 2) * 64;
    const int i0 = blockIdx.x * 64;
    const int jb = (blockIdx.y >> 1) * 32;
    const int hh = blockIdx.y & 1;
    const float* __restrict__ Hf = d_H + 2 * B_SZ * HID;

    #pragma unroll 4
    for (int t = 0; t < 16; ++t) {
        int idx = tid + t * 256;
        int ii = idx & 63, h2 = idx >> 6;
        float2 v = *(const float2*)(Hf + (i0 + ii) * 256 + hh * 128 + 2 * h2);
        sApk[h2 * 72 + ii] = pack_bf2(v.x, v.y);
    }
    #pragma unroll
    for (int t = 0; t < 8; ++t) {
        int idx = tid + t * 256;
        int jj = idx & 31, ii = idx >> 5;
        sX[jj * 72 + ii] = d_X[(i0 + ii) * FEAT + jb + jj];
    }

    const int r2 = tid >> 5;
    const int c4 = (tid & 31) * 4;
    const int hbase = hh * 64;

    #pragma unroll
    for (int p = 0; p < 3; ++p) {
        int jj = p >> 2, hw = p & 3;
        const uint32_t* gp = d_W2bf + (size_t)(hbase + hw * 16 + r2) * W2COLS
                                    + (size_t)(jb + jj) * 128 + c4;
        uint32_t* dp = sBpk + (p & 3) * 2176 + r2 * 136 + c4;
        CP16(smem_u32(dp), gp);
        CP16(smem_u32(dp + 8 * 136), gp + (size_t)8 * W2COLS);
        CP_COMMIT();
    }

    float xacc[8][4] = {};
    float facc[8][4] = {};
    for (int s = 0; s < 128; ++s) {
        CP_WAIT2();
        __syncthreads();
        const uint32_t* bbuf = sBpk + (s & 3) * 2176;
        const int kb2base = (s & 3) * 16;
        #pragma unroll
        for (int ks = 0; ks < 2; ++ks) {
            const int kb2 = kb2base + ks * 8;
            uint32_t a0 = sApk[(kb2 + c) * 72 + iw0 + g];
            uint32_t a1 = sApk[(kb2 + c) * 72 + iw0 + g + 8];
            uint32_t a2 = sApk[(kb2 + c + 4) * 72 + iw0 + g];
            uint32_t a3 = sApk[(kb2 + c + 4) * 72 + iw0 + g + 8];
            #pragma unroll
            for (int t = 0; t < 8; ++t) {
                uint32_t b0 = bbuf[(ks * 8 + c) * 136 + kw0 + t * 8 + g];
                uint32_t b1 = bbuf[(ks * 8 + c + 4) * 136 + kw0 + t * 8 + g];
                asm volatile(
                    "mma.sync.aligned.m16n8k16.row.col.f32.bf16.bf16.f32 "
                    "{%0,%1,%2,%3},{%4,%5,%6,%7},{%8,%9},{%0,%1,%2,%3};"
                    : "+f"(facc[t][0]), "+f"(facc[t][1]),
                      "+f"(facc[t][2]), "+f"(facc[t][3])
                    : "r"(a0), "r"(a1), "r"(a2), "r"(a3), "r"(b0), "r"(b1));
            }
        }
        if (s + 3 < 128) {
            int s3 = s + 3;
            int jj = s3 >> 2, hw = s3 & 3;
            const uint32_t* gp = d_W2bf + (size_t)(hbase + hw * 16 + r2) * W2COLS
                                        + (size_t)(jb + jj) * 128 + c4;
            uint32_t* dp = sBpk + (s3 & 3) * 2176 + r2 * 136 + c4;
            CP16(smem_u32(dp), gp);
            CP16(smem_u32(dp + 8 * 136), gp + (size_t)8 * W2COLS);
        }
        CP_COMMIT();
        if ((s & 3) == 3) {
            int jj = s >> 2;
            float xv0 = sX[jj * 72 + iw0 + g];
            float xv1 = sX[jj * 72 + iw0 + g + 8];
            #pragma unroll
            for (int t = 0; t < 8; ++t) {
                xacc[t][0] = fmaf(xv0, facc[t][0], xacc[t][0]);
                xacc[t][1] = fmaf(xv0, facc[t][1], xacc[t][1]);
                xacc[t][2] = fmaf(xv1, facc[t][2], xacc[t][2]);
                xacc[t][3] = fmaf(xv1, facc[t][3], xacc[t][3]);
                facc[t][0] = 0.f; facc[t][1] = 0.f;
                facc[t][2] = 0.f; facc[t][3] = 0.f;
            }
        }
    }

    float* outp = d_X2p + (size_t)blockIdx.y * (B_SZ * ED) + (size_t)i0 * 128;
    #pragma unroll
    for (int t = 0; t < 8; ++t) {
        int col = kw0 + t * 8 + 2 * c;
        int row0 = iw0 + g, row1 = iw0 + g + 8;
        *(float2*)&outp[row0 * 128 + col] = make_float2(xacc[t][0], xacc[t][1]);
        *(float2*)&outp[row1 * 128 + col] = make_float2(xacc[t][2], xacc[t][3]);
    }
}

__global__ void k_reduce() {
    int idx = blockIdx.x * 256 + threadIdx.x;
    float a = d_fcb[idx];
    #pragma unroll 4
    for (int p = 0; p < NPLANE; ++p) a += d_X2p[(size_t)p * (B_SZ * ED) + idx];
    d_X2[idx] = a;
}

__global__ void k_bn2() {
    int k = threadIdx.x;
    float s = 0.f, ss = 0.f;
    for (int i = 0; i < B_SZ; ++i) {
        float v = d_X2[i * 128 + k]; s += v; ss += v * v;
    }
    const float inv = 1.0f / B_SZ;
    float m = s * inv, var = ss * inv - m * m;
    float istd = rsqrtf(var + 1e-5f);
    for (int i = 0; i < B_SZ; ++i) {
        float v = (d_X2[i * 128 + k] - m) * istd;
        d_Xbn[i * 128 + k] = fmaxf(v, 0.f);
    }
}

__global__ void __launch_bounds__(256, 2) k_final(const float* __restrict__ E2,
                                                  const float* __restrict__ bias,
                                                  float* __restrict__ out) {
    extern __shared__ float sm[];
    float* sAt = sm;
    float* sBt = sm + 16896;
    const int tid = threadIdx.x;
    const int lane = tid & 31, wid = tid >> 5;
    const int g = lane >> 2, c = lane & 3;
    const int iw = wid * 16;
    const int i0 = blockIdx.y * 128, n0 = blockIdx.x * 64;
    #pragma unroll 4
    for (int t = 0; t < 64; ++t) {
        int idx = tid + t * 256;
        int k = idx & 127, ii = idx >> 7;
        sAt[k * 132 + ii] = tf32r(d_Xbn[(i0 + ii) * 128 + k]);
    }
    #pragma unroll 4
    for (int t = 0; t < 32; ++t) {
        int idx = tid + t * 256;
        int k = idx & 127, nn = idx >> 7;
        int n = n0 + nn;
        sBt[k * 72 + nn] = (n < NENT) ? tf32r(E2[(size_t)n * 128 + k]) : 0.f;
    }
    __syncthreads();
    float facc[8][4] = {};
    #pragma unroll
    for (int kb = 0; kb < 128; kb += 8) {
        unsigned a0 = __float_as_uint(sAt[(kb + c) * 132 + iw + g]);
        unsigned a1 = __float_as_uint(sAt[(kb + c) * 132 + iw + g + 8]);
        unsigned a2 = __float_as_uint(sAt[(kb + c + 4) * 132 + iw + g]);
        unsigned a3 = __float_as_uint(sAt[(kb + c + 4) * 132 + iw + g + 8]);
        #pragma unroll
        for (int t = 0; t < 8; ++t) {
            unsigned b0 = __float_as_uint(sBt[(kb + c) * 72 + t * 8 + g]);
            unsigned b1 = __float_as_uint(sBt[(kb + c + 4) * 72 + t * 8 + g]);
            asm volatile(
                "mma.sync.aligned.m16n8k8.row.col.f32.tf32.tf32.f32 "
                "{%0,%1,%2,%3},{%4,%5,%6,%7},{%8,%9},{%0,%1,%2,%3};"
                : "+f"(facc[t][0]), "+f"(facc[t][1]),
                  "+f"(facc[t][2]), "+f"(facc[t][3])
                : "r"(a0), "r"(a1), "r"(a2), "r"(a3), "r"(b0), "r"(b1));
        }
    }
    const int r0 = i0 + iw + g;
    #pragma unroll
    for (int t = 0; t < 8; ++t) {
        int n = n0 + t * 8 + 2 * c;
        if (n < NENT) {
            float bb = bias[n];
            out[(size_t)r0 * NENT + n]       = 1.f / (1.f + __expf(-(facc[t][0] + bb)));
            out[(size_t)(r0 + 8) * NENT + n] = 1.f / (1.f + __expf(-(facc[t][2] + bb)));
        }
        if (n + 1 < NENT) {
            float bb = bias[n + 1];
            out[(size_t)r0 * NENT + n + 1]       = 1.f / (1.f + __expf(-(facc[t][1] + bb)));
            out[(size_t)(r0 + 8) * NENT + n + 1] = 1.f / (1.f + __expf(-(facc[t][3] + bb)));
        }
    }
}

extern "C" void kernel_launch(void* const* d_in, const int* in_sizes, int n_in,
                              void* d_out, int out_size) {
    const int*   e1       = (const int*)d_in[0];
    const int*   r        = (const int*)d_in[1];
    const float* ent      = (const float*)d_in[2];
    const float* rel      = (const float*)d_in[3];
    const float* convw_w1 = (const float*)d_in[4];
    const float* convw_w2 = (const float*)d_in[5];
    const float* convb_w1 = (const float*)d_in[6];
    const float* convb_w2 = (const float*)d_in[7];
    const float* fcw_w1   = (const float*)d_in[8];
    const float* fcw_w2   = (const float*)d_in[9];
    const float* fcb_w1   = (const float*)d_in[10];
    const float* fcb_w2   = (const float*)d_in[11];
    const float* bias     = (const float*)d_in[12];
    float* out = (float*)d_out;

    cudaFuncSetAttribute(k_bigfused, cudaFuncAttributeMaxDynamicSharedMemorySize, 62464);
    cudaFuncSetAttribute(k_final, cudaFuncAttributeMaxDynamicSharedMemorySize, 104448);

    // Fork w2cast (HBM-bound, no deps on smalls) onto a side stream so it
    // overlaps the latency-bound small-kernel chain. Streams/events are
    // host-side objects (no device allocation); pattern is the standard
    // multi-stream capture fork and works identically uncaptured.
    cudaStream_t s2 = 0;
    cudaEvent_t ev0 = 0, ev1 = 0;
    bool fork = (cudaStreamCreateWithFlags(&s2, cudaStreamNonBlocking) == cudaSuccess);
    if (fork) fork = (cudaEventCreateWithFlags(&ev0, cudaEventDisableTiming) == cudaSuccess);
    if (fork) fork = (cudaEventCreateWithFlags(&ev1, cudaEventDisableTiming) == cudaSuccess);

    if (fork) {
        cudaEventRecord(ev0, 0);
        cudaStreamWaitEvent(s2, ev0, 0);
        k_w2cast<<<dim3(336, 128), 256, 0, s2>>>(fcw_w2);
    } else {
        k_w2cast<<<dim3(336, 128), 256>>>(fcw_w2);
    }

    k_gather<<<128, 256>>>(e1, r, ent, rel);
    k_bn0<<<1, 256>>>();
    k_cpg1<<<dim3(4, 4, 4), 256>>>(convw_w1, convb_w1, fcw_w1, fcb_w1);
    k_cpg2<<<dim3(5, 4, 3), 256>>>(convw_w2, convb_w2, fcb_w2);
    k_conv<<<256, 256>>>();

    if (fork) {
        cudaEventRecord(ev1, s2);
        cudaStreamWaitEvent(0, ev1, 0);
    }

    k_bigfused<<<dim3(4, NPLANE), 256, 62464>>>();
    k_reduce<<<128, 256>>>();
    k_bn2<<<1, 128>>>();
    k_final<<<dim3(640, 2), 256, 104448>>>(ent, bias, out);
}

// round 16
// speedup vs baseline: 1.0398x; 1.0398x over previous
#include <cuda_runtime.h>
#include <cuda_bf16.h>
#include <cstdint>

#define B_SZ 256
#define ED   128
#define HID  256
#define FEAT 2688
#define NENT 40943
#define W2COLS 344064   // FEAT*ED
#define NJC  84         // 84 * 32 = 2688 j-chunks
#define NPLANE (NJC * 2)   // j-chunk x h-half partial planes

__device__ float d_E1[B_SZ * ED];
__device__ float d_R[B_SZ * ED];
__device__ float d_stats[2];
__device__ float d_H[4 * B_SZ * HID];      // planes: Hc, Hcb, Hf, Hfb
__device__ float d_filt[B_SZ * 288];
__device__ float d_cbias[B_SZ * 32];
__device__ float d_fcb[B_SZ * ED];
__device__ float d_X[B_SZ * FEAT];
__device__ float d_X2p[NPLANE * B_SZ * ED]; // split (j,h) partials
__device__ float d_X2[B_SZ * ED];
__device__ float d_Xbn[B_SZ * ED];
// W2 pre-packed to bf16 pairs: P[h2][col] = bf2(W2[2h2][col], W2[2h2+1][col])
__device__ uint32_t d_W2bf[128 * W2COLS];  // 176 MB

__device__ __forceinline__ uint32_t pack_bf2(float lo, float hi) {
    __nv_bfloat162 b = __floats2bfloat162_rn(lo, hi);
    return *reinterpret_cast<uint32_t*>(&b);
}
__device__ __forceinline__ float tf32r(float x) {
    unsigned u; asm("cvt.rna.tf32.f32 %0, %1;" : "=r"(u) : "f"(x));
    return __uint_as_float(u);
}
__device__ __forceinline__ uint32_t smem_u32(const void* p) {
    return (uint32_t)__cvta_generic_to_shared(p);
}
#define CP16(d, s) asm volatile("cp.async.cg.shared.global [%0], [%1], 16;" :: "r"(d), "l"(s))
#define CP_COMMIT() asm volatile("cp.async.commit_group;")
#define CP_WAIT2()  asm volatile("cp.async.wait_group 2;")

__global__ void k_gather(const int* __restrict__ e1, const int* __restrict__ r,
                         const float* __restrict__ ent, const float* __restrict__ rel) {
    int idx = blockIdx.x * 256 + threadIdx.x;
    int i = idx >> 7, c = idx & 127;
    d_E1[idx] = ent[(size_t)e1[i] * ED + c];
    d_R[idx]  = rel[(size_t)r[i]  * ED + c];
}

__global__ void k_w2cast(const float* __restrict__ W2) {
    int h2 = blockIdx.y;
    int col = blockIdx.x * 1024 + threadIdx.x * 4;
    const float4 lo = *(const float4*)(W2 + (size_t)(2 * h2) * W2COLS + col);
    const float4 hi = *(const float4*)(W2 + (size_t)(2 * h2 + 1) * W2COLS + col);
    uint4 w = make_uint4(pack_bf2(lo.x, hi.x), pack_bf2(lo.y, hi.y),
                         pack_bf2(lo.z, hi.z), pack_bf2(lo.w, hi.w));
    *(uint4*)&d_W2bf[(size_t)h2 * W2COLS + col] = w;
}

__global__ void k_bn0() {
    __shared__ float rs[8], rss[8];
    int tid = threadIdx.x;
    float s = 0.f, ss = 0.f;
    for (int idx = tid; idx < B_SZ * ED; idx += 256) {
        float v = d_E1[idx]; s += v; ss += v * v;
    }
    for (int o = 16; o; o >>= 1) {
        s  += __shfl_xor_sync(0xffffffffu, s,  o);
        ss += __shfl_xor_sync(0xffffffffu, ss, o);
    }
    if ((tid & 31) == 0) { rs[tid >> 5] = s; rss[tid >> 5] = ss; }
    __syncthreads();
    if (tid == 0) {
        float S = 0.f, SS = 0.f;
        for (int w = 0; w < 8; ++w) { S += rs[w]; SS += rss[w]; }
        const float inv = 1.0f / (B_SZ * ED);
        float m = S * inv, var = SS * inv - m * m;
        d_stats[0] = m; d_stats[1] = rsqrtf(var + 1e-5f);
    }
}

__device__ __forceinline__ void gemm64_body(const float* __restrict__ A,
                                            const float* __restrict__ Bw,
                                            float* __restrict__ C,
                                            int K, int N, int doRelu,
                                            int i0, int n0) {
    __shared__ float sA[16 * 64];
    __shared__ float sB[16 * 64];
    const int tid = threadIdx.x;
    const int ty = tid >> 4, tx = tid & 15;
    float acc[4][4] = {};
    for (int kb = 0; kb < K; kb += 16) {
        #pragma unroll
        for (int t = 0; t < 4; ++t) {
            int idx = tid + t * 256;
            int kk = idx & 15, ii = idx >> 4;
            sA[kk * 64 + ii] = A[(i0 + ii) * K + kb + kk];
            int nn = idx & 63, kk2 = idx >> 6;
            int n = n0 + nn;
            sB[kk2 * 64 + nn] = (n < N) ? Bw[(size_t)(kb + kk2) * N + n] : 0.f;
        }
        __syncthreads();
        #pragma unroll
        for (int kk = 0; kk < 16; ++kk) {
            float a[4], b[4];
            #pragma unroll
            for (int u = 0; u < 4; ++u) a[u] = sA[kk * 64 + ty * 4 + u];
            #pragma unroll
            for (int v = 0; v < 4; ++v) b[v] = sB[kk * 64 + tx * 4 + v];
            #pragma unroll
            for (int u = 0; u < 4; ++u)
                #pragma unroll
                for (int v = 0; v < 4; ++v)
                    acc[u][v] = fmaf(a[u], b[v], acc[u][v]);
        }
        __syncthreads();
    }
    #pragma unroll
    for (int u = 0; u < 4; ++u) {
        int row = i0 + ty * 4 + u;
        #pragma unroll
        for (int v = 0; v < 4; ++v) {
            int col = n0 + tx * 4 + v;
            if (col < N) {
                float val = acc[u][v];
                if (doRelu) val = fmaxf(val, 0.f);
                C[(size_t)row * N + col] = val;
            }
        }
    }
}

__global__ void k_cpg1(const float* __restrict__ w0, const float* __restrict__ w1,
                       const float* __restrict__ w2, const float* __restrict__ w3) {
    const float* Bw = (blockIdx.z == 0) ? w0 : (blockIdx.z == 1) ? w1
                    : (blockIdx.z == 2) ? w2 : w3;
    float* C = d_H + (size_t)blockIdx.z * (B_SZ * HID);
    gemm64_body(d_R, Bw, C, 128, 256, 1, blockIdx.y * 64, blockIdx.x * 64);
}

__global__ void k_cpg2(const float* __restrict__ convw_w2,
                       const float* __restrict__ convb_w2,
                       const float* __restrict__ fcb_w2) {
    int z = blockIdx.z;
    const float* A; const float* Bw; float* C; int N;
    if (z == 0)      { A = d_H;                  Bw = convw_w2; C = d_filt;  N = 288; }
    else if (z == 1) { A = d_H + B_SZ * HID;     Bw = convb_w2; C = d_cbias; N = 32;  }
    else             { A = d_H + 3 * B_SZ * HID; Bw = fcb_w2;   C = d_fcb;   N = 128; }
    int n0 = blockIdx.x * 64;
    if (n0 >= N) return;
    gemm64_body(A, Bw, C, 256, N, 0, blockIdx.y * 64, n0);
}

__global__ void k_conv() {
    __shared__ float sx[128];
    __shared__ float sf[288];
    __shared__ float scb[32];
    const int i = blockIdx.x, tid = threadIdx.x;
    const float mean = d_stats[0], istd = d_stats[1];
    if (tid < 128) sx[tid] = (d_E1[i * 128 + tid] - mean) * istd;
    if (tid < 32)  scb[tid] = d_cbias[i * 32 + tid];
    for (int q = tid; q < 288; q += 256) sf[q] = d_filt[i * 288 + q];
    __syncthreads();
    for (int oi = tid; oi < FEAT; oi += 256) {
        int c = oi / 84, rem = oi - c * 84;
        int y = rem / 14, x = rem - y * 14;
        float a = scb[c];
        #pragma unroll
        for (int ky = 0; ky < 3; ++ky)
            #pragma unroll
            for (int kx = 0; kx < 3; ++kx)
                a = fmaf(sx[(y + ky) * 16 + (x + kx)], sf[c * 9 + ky * 3 + kx], a);
        d_X[i * FEAT + oi] = fmaxf(a, 0.f);
    }
}

// ---------- dominant contraction: bf16 mma m16n8k16, warp tile 32i x 32k ----------
// Block: 64 i x 128 k x 32 j x 128 h-half. 8 warps = 2 i-pos x 4 k-pos.
// B fragments reused across 2 m-frags in registers (crossbar -20% vs 16x64).
__global__ void __launch_bounds__(256, 2) k_bigfused() {
    extern __shared__ uint32_t smw[];
    uint32_t* sApk = smw;                    // [h2=64][72]
    uint32_t* sBpk = smw + 4608;             // 4 x [k2=16][136]
    float*    sX   = (float*)(smw + 4608 + 8704);   // [jj=32][72]
    const int tid = threadIdx.x;
    const int lane = tid & 31, wid = tid >> 5;
    const int g = lane >> 2, c = lane & 3;
    const int iw0 = (wid & 1) * 32;          // warp i-offset (32 rows)
    const int kw0 = (wid >> 1) * 32;         // warp k-offset (32 cols)
    const int i0 = blockIdx.x * 64;
    const int jb = (blockIdx.y >> 1) * 32;
    const int hh = blockIdx.y & 1;
    const float* __restrict__ Hf = d_H + 2 * B_SZ * HID;

    #pragma unroll 4
    for (int t = 0; t < 16; ++t) {
        int idx = tid + t * 256;
        int ii = idx & 63, h2 = idx >> 6;
        float2 v = *(const float2*)(Hf + (i0 + ii) * 256 + hh * 128 + 2 * h2);
        sApk[h2 * 72 + ii] = pack_bf2(v.x, v.y);
    }
    #pragma unroll
    for (int t = 0; t < 8; ++t) {
        int idx = tid + t * 256;
        int jj = idx & 31, ii = idx >> 5;
        sX[jj * 72 + ii] = d_X[(i0 + ii) * FEAT + jb + jj];
    }

    const int r2 = tid >> 5;
    const int c4 = (tid & 31) * 4;
    const int hbase = hh * 64;

    #pragma unroll
    for (int p = 0; p < 3; ++p) {
        int jj = p >> 2, hw = p & 3;
        const uint32_t* gp = d_W2bf + (size_t)(hbase + hw * 16 + r2) * W2COLS
                                    + (size_t)(jb + jj) * 128 + c4;
        uint32_t* dp = sBpk + (p & 3) * 2176 + r2 * 136 + c4;
        CP16(smem_u32(dp), gp);
        CP16(smem_u32(dp + 8 * 136), gp + (size_t)8 * W2COLS);
        CP_COMMIT();
    }

    float xacc[2][4][4] = {};
    float facc[2][4][4] = {};
    for (int s = 0; s < 128; ++s) {
        CP_WAIT2();
        __syncthreads();
        const uint32_t* bbuf = sBpk + (s & 3) * 2176;
        const int kb2base = (s & 3) * 16;
        #pragma unroll
        for (int ks = 0; ks < 2; ++ks) {
            const int kb2 = kb2base + ks * 8;
            uint32_t a[2][4];
            #pragma unroll
            for (int m = 0; m < 2; ++m) {
                int ibm = iw0 + m * 16;
                a[m][0] = sApk[(kb2 + c) * 72 + ibm + g];
                a[m][1] = sApk[(kb2 + c) * 72 + ibm + g + 8];
                a[m][2] = sApk[(kb2 + c + 4) * 72 + ibm + g];
                a[m][3] = sApk[(kb2 + c + 4) * 72 + ibm + g + 8];
            }
            #pragma unroll
            for (int t = 0; t < 4; ++t) {
                uint32_t b0 = bbuf[(ks * 8 + c) * 136 + kw0 + t * 8 + g];
                uint32_t b1 = bbuf[(ks * 8 + c + 4) * 136 + kw0 + t * 8 + g];
                #pragma unroll
                for (int m = 0; m < 2; ++m) {
                    asm volatile(
                        "mma.sync.aligned.m16n8k16.row.col.f32.bf16.bf16.f32 "
                        "{%0,%1,%2,%3},{%4,%5,%6,%7},{%8,%9},{%0,%1,%2,%3};"
                        : "+f"(facc[m][t][0]), "+f"(facc[m][t][1]),
                          "+f"(facc[m][t][2]), "+f"(facc[m][t][3])
                        : "r"(a[m][0]), "r"(a[m][1]), "r"(a[m][2]), "r"(a[m][3]),
                          "r"(b0), "r"(b1));
                }
            }
        }
        if (s + 3 < 128) {
            int s3 = s + 3;
            int jj = s3 >> 2, hw = s3 & 3;
            const uint32_t* gp = d_W2bf + (size_t)(hbase + hw * 16 + r2) * W2COLS
                                        + (size_t)(jb + jj) * 128 + c4;
            uint32_t* dp = sBpk + (s3 & 3) * 2176 + r2 * 136 + c4;
            CP16(smem_u32(dp), gp);
            CP16(smem_u32(dp + 8 * 136), gp + (size_t)8 * W2COLS);
        }
        CP_COMMIT();
        if ((s & 3) == 3) {                 // end of one j: contract with X
            int jj = s >> 2;
            #pragma unroll
            for (int m = 0; m < 2; ++m) {
                float xv0 = sX[jj * 72 + iw0 + m * 16 + g];
                float xv1 = sX[jj * 72 + iw0 + m * 16 + g + 8];
                #pragma unroll
                for (int t = 0; t < 4; ++t) {
                    xacc[m][t][0] = fmaf(xv0, facc[m][t][0], xacc[m][t][0]);
                    xacc[m][t][1] = fmaf(xv0, facc[m][t][1], xacc[m][t][1]);
                    xacc[m][t][2] = fmaf(xv1, facc[m][t][2], xacc[m][t][2]);
                    xacc[m][t][3] = fmaf(xv1, facc[m][t][3], xacc[m][t][3]);
                    facc[m][t][0] = 0.f; facc[m][t][1] = 0.f;
                    facc[m][t][2] = 0.f; facc[m][t][3] = 0.f;
                }
            }
        }
    }

    float* outp = d_X2p + (size_t)blockIdx.y * (B_SZ * ED) + (size_t)i0 * 128;
    #pragma unroll
    for (int m = 0; m < 2; ++m) {
        int row0 = iw0 + m * 16 + g, row1 = row0 + 8;
        #pragma unroll
        for (int t = 0; t < 4; ++t) {
            int col = kw0 + t * 8 + 2 * c;
            *(float2*)&outp[row0 * 128 + col] = make_float2(xacc[m][t][0], xacc[m][t][1]);
            *(float2*)&outp[row1 * 128 + col] = make_float2(xacc[m][t][2], xacc[m][t][3]);
        }
    }
}

__global__ void k_reduce() {
    int idx = blockIdx.x * 256 + threadIdx.x;
    float a = d_fcb[idx];
    #pragma unroll 4
    for (int p = 0; p < NPLANE; ++p) a += d_X2p[(size_t)p * (B_SZ * ED) + idx];
    d_X2[idx] = a;
}

__global__ void k_bn2() {
    int k = threadIdx.x;
    float s = 0.f, ss = 0.f;
    for (int i = 0; i < B_SZ; ++i) {
        float v = d_X2[i * 128 + k]; s += v; ss += v * v;
    }
    const float inv = 1.0f / B_SZ;
    float m = s * inv, var = ss * inv - m * m;
    float istd = rsqrtf(var + 1e-5f);
    for (int i = 0; i < B_SZ; ++i) {
        float v = (d_X2[i * 128 + k] - m) * istd;
        d_Xbn[i * 128 + k] = fmaxf(v, 0.f);
    }
}

__global__ void __launch_bounds__(256, 2) k_final(const float* __restrict__ E2,
                                                  const float* __restrict__ bias,
                                                  float* __restrict__ out) {
    extern __shared__ float sm[];
    float* sAt = sm;
    float* sBt = sm + 16896;
    const int tid = threadIdx.x;
    const int lane = tid & 31, wid = tid >> 5;
    const int g = lane >> 2, c = lane & 3;
    const int iw = wid * 16;
    const int i0 = blockIdx.y * 128, n0 = blockIdx.x * 64;
    #pragma unroll 4
    for (int t = 0; t < 64; ++t) {
        int idx = tid + t * 256;
        int k = idx & 127, ii = idx >> 7;
        sAt[k * 132 + ii] = tf32r(d_Xbn[(i0 + ii) * 128 + k]);
    }
    #pragma unroll 4
    for (int t = 0; t < 32; ++t) {
        int idx = tid + t * 256;
        int k = idx & 127, nn = idx >> 7;
        int n = n0 + nn;
        sBt[k * 72 + nn] = (n < NENT) ? tf32r(E2[(size_t)n * 128 + k]) : 0.f;
    }
    __syncthreads();
    float facc[8][4] = {};
    #pragma unroll
    for (int kb = 0; kb < 128; kb += 8) {
        unsigned a0 = __float_as_uint(sAt[(kb + c) * 132 + iw + g]);
        unsigned a1 = __float_as_uint(sAt[(kb + c) * 132 + iw + g + 8]);
        unsigned a2 = __float_as_uint(sAt[(kb + c + 4) * 132 + iw + g]);
        unsigned a3 = __float_as_uint(sAt[(kb + c + 4) * 132 + iw + g + 8]);
        #pragma unroll
        for (int t = 0; t < 8; ++t) {
            unsigned b0 = __float_as_uint(sBt[(kb + c) * 72 + t * 8 + g]);
            unsigned b1 = __float_as_uint(sBt[(kb + c + 4) * 72 + t * 8 + g]);
            asm volatile(
                "mma.sync.aligned.m16n8k8.row.col.f32.tf32.tf32.f32 "
                "{%0,%1,%2,%3},{%4,%5,%6,%7},{%8,%9},{%0,%1,%2,%3};"
                : "+f"(facc[t][0]), "+f"(facc[t][1]),
                  "+f"(facc[t][2]), "+f"(facc[t][3])
                : "r"(a0), "r"(a1), "r"(a2), "r"(a3), "r"(b0), "r"(b1));
        }
    }
    const int r0 = i0 + iw + g;
    #pragma unroll
    for (int t = 0; t < 8; ++t) {
        int n = n0 + t * 8 + 2 * c;
        if (n < NENT) {
            float bb = bias[n];
            out[(size_t)r0 * NENT + n]       = 1.f / (1.f + __expf(-(facc[t][0] + bb)));
            out[(size_t)(r0 + 8) * NENT + n] = 1.f / (1.f + __expf(-(facc[t][2] + bb)));
        }
        if (n + 1 < NENT) {
            float bb = bias[n + 1];
            out[(size_t)r0 * NENT + n + 1]       = 1.f / (1.f + __expf(-(facc[t][1] + bb)));
            out[(size_t)(r0 + 8) * NENT + n + 1] = 1.f / (1.f + __expf(-(facc[t][3] + bb)));
        }
    }
}

extern "C" void kernel_launch(void* const* d_in, const int* in_sizes, int n_in,
                              void* d_out, int out_size) {
    const int*   e1       = (const int*)d_in[0];
    const int*   r        = (const int*)d_in[1];
    const float* ent      = (const float*)d_in[2];
    const float* rel      = (const float*)d_in[3];
    const float* convw_w1 = (const float*)d_in[4];
    const float* convw_w2 = (const float*)d_in[5];
    const float* convb_w1 = (const float*)d_in[6];
    const float* convb_w2 = (const float*)d_in[7];
    const float* fcw_w1   = (const float*)d_in[8];
    const float* fcw_w2   = (const float*)d_in[9];
    const float* fcb_w1   = (const float*)d_in[10];
    const float* fcb_w2   = (const float*)d_in[11];
    const float* bias     = (const float*)d_in[12];
    float* out = (float*)d_out;

    cudaFuncSetAttribute(k_bigfused, cudaFuncAttributeMaxDynamicSharedMemorySize, 62464);
    cudaFuncSetAttribute(k_final, cudaFuncAttributeMaxDynamicSharedMemorySize, 104448);

    k_w2cast<<<dim3(336, 128), 256>>>(fcw_w2);
    k_gather<<<128, 256>>>(e1, r, ent, rel);
    k_bn0<<<1, 256>>>();
    k_cpg1<<<dim3(4, 4, 4), 256>>>(convw_w1, convb_w1, fcw_w1, fcb_w1);
    k_cpg2<<<dim3(5, 4, 3), 256>>>(convw_w2, convb_w2, fcb_w2);
    k_conv<<<256, 256>>>();
    k_bigfused<<<dim3(4, NPLANE), 256, 62464>>>();
    k_reduce<<<128, 256>>>();
    k_bn2<<<1, 128>>>();
    k_final<<<dim3(640, 2), 256, 104448>>>(ent, bias, out);
}

// round 17
// speedup vs baseline: 1.1289x; 1.0857x over previous
#include <cuda_runtime.h>
#include <cuda_bf16.h>
#include <cstdint>

#define B_SZ 256
#define ED   128
#define HID  256
#define FEAT 2688
#define NENT 40943
#define W2COLS 344064   // FEAT*ED
#define NJ2  1344       // FEAT/2 packed j-pairs
#define TN   32768      // T columns = 256h * 128k

__device__ float d_E1[B_SZ * ED];
__device__ float d_R[B_SZ * ED];
__device__ float d_stats[2];
__device__ float d_H[4 * B_SZ * HID];      // planes: Hc, Hcb, Hf, Hfb
__device__ float d_filt[B_SZ * 288];
__device__ float d_cbias[B_SZ * 32];
__device__ float d_fcb[B_SZ * ED];
__device__ float d_X[B_SZ * FEAT];
__device__ uint32_t d_Xbf[NJ2 * B_SZ];     // X bf16-packed [j2][i]
__device__ float d_T[(size_t)B_SZ * TN];   // T = X @ Wt  (33.5 MB)
__device__ float d_X2[B_SZ * ED];
__device__ float d_Xbn[B_SZ * ED];
// Wt[j2][n] = pack_bf2(W2[h, 2j2*128+k], W2[h, (2j2+1)*128+k]), n = h*128+k
__device__ uint32_t d_Wt[(size_t)NJ2 * TN];   // 176 MB

__device__ __forceinline__ uint32_t pack_bf2(float lo, float hi) {
    __nv_bfloat162 b = __floats2bfloat162_rn(lo, hi);
    return *reinterpret_cast<uint32_t*>(&b);
}
__device__ __forceinline__ float tf32r(float x) {
    unsigned u; asm("cvt.rna.tf32.f32 %0, %1;" : "=r"(u) : "f"(x));
    return __uint_as_float(u);
}
__device__ __forceinline__ uint32_t smem_u32(const void* p) {
    return (uint32_t)__cvta_generic_to_shared(p);
}
#define CP16(d, s) asm volatile("cp.async.cg.shared.global [%0], [%1], 16;" :: "r"(d), "l"(s))
#define CP_COMMIT() asm volatile("cp.async.commit_group;")
#define CP_WAIT2()  asm volatile("cp.async.wait_group 2;")

__global__ void k_gather(const int* __restrict__ e1, const int* __restrict__ r,
                         const float* __restrict__ ent, const float* __restrict__ rel) {
    int idx = blockIdx.x * 256 + threadIdx.x;
    int i = idx >> 7, c = idx & 127;
    d_E1[idx] = ent[(size_t)e1[i] * ED + c];
    d_R[idx]  = rel[(size_t)r[i]  * ED + c];
}

// Wt[j2][n]: pack W2 along j (GEMM K dim). grid (32, 1344), 256 thr.
__global__ void k_w2cast(const float* __restrict__ W2) {
    int j2 = blockIdx.y;
    int n = blockIdx.x * 1024 + threadIdx.x * 4;
    int h = n >> 7, k = n & 127;
    const float* p0 = W2 + (size_t)h * W2COLS + (size_t)(2 * j2) * 128 + k;
    float4 lo = *(const float4*)p0;
    float4 hi = *(const float4*)(p0 + 128);
    uint4 w = make_uint4(pack_bf2(lo.x, hi.x), pack_bf2(lo.y, hi.y),
                         pack_bf2(lo.z, hi.z), pack_bf2(lo.w, hi.w));
    *(uint4*)&d_Wt[(size_t)j2 * TN + n] = w;
}

__global__ void k_bn0() {
    __shared__ float rs[8], rss[8];
    int tid = threadIdx.x;
    float s = 0.f, ss = 0.f;
    for (int idx = tid; idx < B_SZ * ED; idx += 256) {
        float v = d_E1[idx]; s += v; ss += v * v;
    }
    for (int o = 16; o; o >>= 1) {
        s  += __shfl_xor_sync(0xffffffffu, s,  o);
        ss += __shfl_xor_sync(0xffffffffu, ss, o);
    }
    if ((tid & 31) == 0) { rs[tid >> 5] = s; rss[tid >> 5] = ss; }
    __syncthreads();
    if (tid == 0) {
        float S = 0.f, SS = 0.f;
        for (int w = 0; w < 8; ++w) { S += rs[w]; SS += rss[w]; }
        const float inv = 1.0f / (B_SZ * ED);
        float m = S * inv, var = SS * inv - m * m;
        d_stats[0] = m; d_stats[1] = rsqrtf(var + 1e-5f);
    }
}

__device__ __forceinline__ void gemm64_body(const float* __restrict__ A,
                                            const float* __restrict__ Bw,
                                            float* __restrict__ C,
                                            int K, int N, int doRelu,
                                            int i0, int n0) {
    __shared__ float sA[16 * 64];
    __shared__ float sB[16 * 64];
    const int tid = threadIdx.x;
    const int ty = tid >> 4, tx = tid & 15;
    float acc[4][4] = {};
    for (int kb = 0; kb < K; kb += 16) {
        #pragma unroll
        for (int t = 0; t < 4; ++t) {
            int idx = tid + t * 256;
            int kk = idx & 15, ii = idx >> 4;
            sA[kk * 64 + ii] = A[(i0 + ii) * K + kb + kk];
            int nn = idx & 63, kk2 = idx >> 6;
            int n = n0 + nn;
            sB[kk2 * 64 + nn] = (n < N) ? Bw[(size_t)(kb + kk2) * N + n] : 0.f;
        }
        __syncthreads();
        #pragma unroll
        for (int kk = 0; kk < 16; ++kk) {
            float a[4], b[4];
            #pragma unroll
            for (int u = 0; u < 4; ++u) a[u] = sA[kk * 64 + ty * 4 + u];
            #pragma unroll
            for (int v = 0; v < 4; ++v) b[v] = sB[kk * 64 + tx * 4 + v];
            #pragma unroll
            for (int u = 0; u < 4; ++u)
                #pragma unroll
                for (int v = 0; v < 4; ++v)
                    acc[u][v] = fmaf(a[u], b[v], acc[u][v]);
        }
        __syncthreads();
    }
    #pragma unroll
    for (int u = 0; u < 4; ++u) {
        int row = i0 + ty * 4 + u;
        #pragma unroll
        for (int v = 0; v < 4; ++v) {
            int col = n0 + tx * 4 + v;
            if (col < N) {
                float val = acc[u][v];
                if (doRelu) val = fmaxf(val, 0.f);
                C[(size_t)row * N + col] = val;
            }
        }
    }
}

__global__ void k_cpg1(const float* __restrict__ w0, const float* __restrict__ w1,
                       const float* __restrict__ w2, const float* __restrict__ w3) {
    const float* Bw = (blockIdx.z == 0) ? w0 : (blockIdx.z == 1) ? w1
                    : (blockIdx.z == 2) ? w2 : w3;
    float* C = d_H + (size_t)blockIdx.z * (B_SZ * HID);
    gemm64_body(d_R, Bw, C, 128, 256, 1, blockIdx.y * 64, blockIdx.x * 64);
}

__global__ void k_cpg2(const float* __restrict__ convw_w2,
                       const float* __restrict__ convb_w2,
                       const float* __restrict__ fcb_w2) {
    int z = blockIdx.z;
    const float* A; const float* Bw; float* C; int N;
    if (z == 0)      { A = d_H;                  Bw = convw_w2; C = d_filt;  N = 288; }
    else if (z == 1) { A = d_H + B_SZ * HID;     Bw = convb_w2; C = d_cbias; N = 32;  }
    else             { A = d_H + 3 * B_SZ * HID; Bw = fcb_w2;   C = d_fcb;   N = 128; }
    int n0 = blockIdx.x * 64;
    if (n0 >= N) return;
    gemm64_body(A, Bw, C, 256, N, 0, blockIdx.y * 64, n0);
}

__global__ void k_conv() {
    __shared__ float sx[128];
    __shared__ float sf[288];
    __shared__ float scb[32];
    const int i = blockIdx.x, tid = threadIdx.x;
    const float mean = d_stats[0], istd = d_stats[1];
    if (tid < 128) sx[tid] = (d_E1[i * 128 + tid] - mean) * istd;
    if (tid < 32)  scb[tid] = d_cbias[i * 32 + tid];
    for (int q = tid; q < 288; q += 256) sf[q] = d_filt[i * 288 + q];
    __syncthreads();
    for (int oi = tid; oi < FEAT; oi += 256) {
        int c = oi / 84, rem = oi - c * 84;
        int y = rem / 14, x = rem - y * 14;
        float a = scb[c];
        #pragma unroll
        for (int ky = 0; ky < 3; ++ky)
            #pragma unroll
            for (int kx = 0; kx < 3; ++kx)
                a = fmaf(sx[(y + ky) * 16 + (x + kx)], sf[c * 9 + ky * 3 + kx], a);
        d_X[i * FEAT + oi] = fmaxf(a, 0.f);
    }
}

// pack X -> bf16x2 [j2][i]; grid 256 (i), 256 thr (j2)
__global__ void k_xpack() {
    int i = blockIdx.x;
    for (int j2 = threadIdx.x; j2 < NJ2; j2 += 256) {
        float2 v = *(const float2*)&d_X[i * FEAT + 2 * j2];
        d_Xbf[j2 * B_SZ + i] = pack_bf2(v.x, v.y);
    }
}

// ---------- T = X @ Wt : bf16 mma m16n8k16, plain GEMM, cp.async ring ----------
// Block 128i x 128n, 8 warps = 4i x 2n, warp 32i x 64n. K = 1344 j2, 84 stages.
#define GT_SMEM (8 * 2176 * 4)
__global__ void __launch_bounds__(256, 2) k_gemmT() {
    extern __shared__ uint32_t smw[];
    uint32_t* sA = smw;              // 4 x [16 j2][136]
    uint32_t* sB = smw + 4 * 2176;   // 4 x [16 j2][136]
    const int tid = threadIdx.x;
    const int lane = tid & 31, wid = tid >> 5;
    const int g = lane >> 2, c = lane & 3;
    const int iw0 = (wid & 3) * 32;
    const int nw0 = (wid >> 2) * 64;
    const int i0 = blockIdx.x * 128;       // grid.x = 2
    const int n0 = blockIdx.y * 128;       // grid.y = 256
    const int r2 = tid >> 5;
    const int c4 = (tid & 31) * 4;

    #pragma unroll
    for (int p = 0; p < 3; ++p) {
        const uint32_t* ga = d_Xbf + (size_t)(p * 16 + r2) * B_SZ + i0 + c4;
        const uint32_t* gb = d_Wt + (size_t)(p * 16 + r2) * TN + n0 + c4;
        uint32_t da = smem_u32(sA + p * 2176 + r2 * 136 + c4);
        uint32_t db = smem_u32(sB + p * 2176 + r2 * 136 + c4);
        CP16(da, ga);
        CP16(da + 8 * 136 * 4, ga + (size_t)8 * B_SZ);
        CP16(db, gb);
        CP16(db + 8 * 136 * 4, gb + (size_t)8 * TN);
        CP_COMMIT();
    }

    float facc[2][8][4] = {};
    for (int s = 0; s < 84; ++s) {
        CP_WAIT2();
        __syncthreads();
        const uint32_t* abuf = sA + (s & 3) * 2176;
        const uint32_t* bbuf = sB + (s & 3) * 2176;
        #pragma unroll
        for (int ks = 0; ks < 2; ++ks) {
            const int kb2 = ks * 8;
            uint32_t a[2][4];
            #pragma unroll
            for (int m = 0; m < 2; ++m) {
                int ibm = iw0 + m * 16;
                a[m][0] = abuf[(kb2 + c) * 136 + ibm + g];
                a[m][1] = abuf[(kb2 + c) * 136 + ibm + g + 8];
                a[m][2] = abuf[(kb2 + c + 4) * 136 + ibm + g];
                a[m][3] = abuf[(kb2 + c + 4) * 136 + ibm + g + 8];
            }
            #pragma unroll
            for (int t = 0; t < 8; ++t) {
                uint32_t b0 = bbuf[(kb2 + c) * 136 + nw0 + t * 8 + g];
                uint32_t b1 = bbuf[(kb2 + c + 4) * 136 + nw0 + t * 8 + g];
                #pragma unroll
                for (int m = 0; m < 2; ++m) {
                    asm volatile(
                        "mma.sync.aligned.m16n8k16.row.col.f32.bf16.bf16.f32 "
                        "{%0,%1,%2,%3},{%4,%5,%6,%7},{%8,%9},{%0,%1,%2,%3};"
                        : "+f"(facc[m][t][0]), "+f"(facc[m][t][1]),
                          "+f"(facc[m][t][2]), "+f"(facc[m][t][3])
                        : "r"(a[m][0]), "r"(a[m][1]), "r"(a[m][2]), "r"(a[m][3]),
                          "r"(b0), "r"(b1));
                }
            }
        }
        if (s + 3 < 84) {
            int s3 = s + 3;
            const uint32_t* ga = d_Xbf + (size_t)(s3 * 16 + r2) * B_SZ + i0 + c4;
            const uint32_t* gb = d_Wt + (size_t)(s3 * 16 + r2) * TN + n0 + c4;
            uint32_t da = smem_u32(sA + (s3 & 3) * 2176 + r2 * 136 + c4);
            uint32_t db = smem_u32(sB + (s3 & 3) * 2176 + r2 * 136 + c4);
            CP16(da, ga);
            CP16(da + 8 * 136 * 4, ga + (size_t)8 * B_SZ);
            CP16(db, gb);
            CP16(db + 8 * 136 * 4, gb + (size_t)8 * TN);
        }
        CP_COMMIT();
    }

    #pragma unroll
    for (int m = 0; m < 2; ++m) {
        int row0 = i0 + iw0 + m * 16 + g, row1 = row0 + 8;
        #pragma unroll
        for (int t = 0; t < 8; ++t) {
            int col = n0 + nw0 + t * 8 + 2 * c;
            *(float2*)&d_T[(size_t)row0 * TN + col] =
                make_float2(facc[m][t][0], facc[m][t][1]);
            *(float2*)&d_T[(size_t)row1 * TN + col] =
                make_float2(facc[m][t][2], facc[m][t][3]);
        }
    }
}

// X2[i,k] = fcb[i,k] + sum_h Hf[i,h] * T[i, h*128+k]; grid 256 (i), 128 thr (k)
__global__ void k_epi() {
    __shared__ float sHf[256];
    const int i = blockIdx.x, k = threadIdx.x;
    const float* Hf = d_H + 2 * B_SZ * HID;
    sHf[k] = Hf[i * 256 + k];
    sHf[k + 128] = Hf[i * 256 + k + 128];
    __syncthreads();
    float acc = d_fcb[i * 128 + k];
    const float* Trow = d_T + (size_t)i * TN + k;
    #pragma unroll 8
    for (int h = 0; h < 256; ++h)
        acc = fmaf(sHf[h], Trow[(size_t)h * 128], acc);
    d_X2[i * 128 + k] = acc;
}

__global__ void k_bn2() {
    int k = threadIdx.x;
    float s = 0.f, ss = 0.f;
    for (int i = 0; i < B_SZ; ++i) {
        float v = d_X2[i * 128 + k]; s += v; ss += v * v;
    }
    const float inv = 1.0f / B_SZ;
    float m = s * inv, var = ss * inv - m * m;
    float istd = rsqrtf(var + 1e-5f);
    for (int i = 0; i < B_SZ; ++i) {
        float v = (d_X2[i * 128 + k] - m) * istd;
        d_Xbn[i * 128 + k] = fmaxf(v, 0.f);
    }
}

__global__ void __launch_bounds__(256, 2) k_final(const float* __restrict__ E2,
                                                  const float* __restrict__ bias,
                                                  float* __restrict__ out) {
    extern __shared__ float sm[];
    float* sAt = sm;
    float* sBt = sm + 16896;
    const int tid = threadIdx.x;
    const int lane = tid & 31, wid = tid >> 5;
    const int g = lane >> 2, c = lane & 3;
    const int iw = wid * 16;
    const int i0 = blockIdx.y * 128, n0 = blockIdx.x * 64;
    #pragma unroll 4
    for (int t = 0; t < 64; ++t) {
        int idx = tid + t * 256;
        int k = idx & 127, ii = idx >> 7;
        sAt[k * 132 + ii] = tf32r(d_Xbn[(i0 + ii) * 128 + k]);
    }
    #pragma unroll 4
    for (int t = 0; t < 32; ++t) {
        int idx = tid + t * 256;
        int k = idx & 127, nn = idx >> 7;
        int n = n0 + nn;
        sBt[k * 72 + nn] = (n < NENT) ? tf32r(E2[(size_t)n * 128 + k]) : 0.f;
    }
    __syncthreads();
    float facc[8][4] = {};
    #pragma unroll
    for (int kb = 0; kb < 128; kb += 8) {
        unsigned a0 = __float_as_uint(sAt[(kb + c) * 132 + iw + g]);
        unsigned a1 = __float_as_uint(sAt[(kb + c) * 132 + iw + g + 8]);
        unsigned a2 = __float_as_uint(sAt[(kb + c + 4) * 132 + iw + g]);
        unsigned a3 = __float_as_uint(sAt[(kb + c + 4) * 132 + iw + g + 8]);
        #pragma unroll
        for (int t = 0; t < 8; ++t) {
            unsigned b0 = __float_as_uint(sBt[(kb + c) * 72 + t * 8 + g]);
            unsigned b1 = __float_as_uint(sBt[(kb + c + 4) * 72 + t * 8 + g]);
            asm volatile(
                "mma.sync.aligned.m16n8k8.row.col.f32.tf32.tf32.f32 "
                "{%0,%1,%2,%3},{%4,%5,%6,%7},{%8,%9},{%0,%1,%2,%3};"
                : "+f"(facc[t][0]), "+f"(facc[t][1]),
                  "+f"(facc[t][2]), "+f"(facc[t][3])
                : "r"(a0), "r"(a1), "r"(a2), "r"(a3), "r"(b0), "r"(b1));
        }
    }
    const int r0 = i0 + iw + g;
    #pragma unroll
    for (int t = 0; t < 8; ++t) {
        int n = n0 + t * 8 + 2 * c;
        if (n < NENT) {
            float bb = bias[n];
            out[(size_t)r0 * NENT + n]       = 1.f / (1.f + __expf(-(facc[t][0] + bb)));
            out[(size_t)(r0 + 8) * NENT + n] = 1.f / (1.f + __expf(-(facc[t][2] + bb)));
        }
        if (n + 1 < NENT) {
            float bb = bias[n + 1];
            out[(size_t)r0 * NENT + n + 1]       = 1.f / (1.f + __expf(-(facc[t][1] + bb)));
            out[(size_t)(r0 + 8) * NENT + n + 1] = 1.f / (1.f + __expf(-(facc[t][3] + bb)));
        }
    }
}

extern "C" void kernel_launch(void* const* d_in, const int* in_sizes, int n_in,
                              void* d_out, int out_size) {
    const int*   e1       = (const int*)d_in[0];
    const int*   r        = (const int*)d_in[1];
    const float* ent      = (const float*)d_in[2];
    const float* rel      = (const float*)d_in[3];
    const float* convw_w1 = (const float*)d_in[4];
    const float* convw_w2 = (const float*)d_in[5];
    const float* convb_w1 = (const float*)d_in[6];
    const float* convb_w2 = (const float*)d_in[7];
    const float* fcw_w1   = (const float*)d_in[8];
    const float* fcw_w2   = (const float*)d_in[9];
    const float* fcb_w1   = (const float*)d_in[10];
    const float* fcb_w2   = (const float*)d_in[11];
    const float* bias     = (const float*)d_in[12];
    float* out = (float*)d_out;

    cudaFuncSetAttribute(k_gemmT, cudaFuncAttributeMaxDynamicSharedMemorySize, GT_SMEM);
    cudaFuncSetAttribute(k_final, cudaFuncAttributeMaxDynamicSharedMemorySize, 104448);

    k_w2cast<<<dim3(32, NJ2), 256>>>(fcw_w2);
    k_gather<<<128, 256>>>(e1, r, ent, rel);
    k_bn0<<<1, 256>>>();
    k_cpg1<<<dim3(4, 4, 4), 256>>>(convw_w1, convb_w1, fcw_w1, fcb_w1);
    k_cpg2<<<dim3(5, 4, 3), 256>>>(convw_w2, convb_w2, fcb_w2);
    k_conv<<<256, 256>>>();
    k_xpack<<<256, 256>>>();
    k_gemmT<<<dim3(2, 256), 256, GT_SMEM>>>();
    k_epi<<<256, 128>>>();
    k_bn2<<<1, 128>>>();
    k_final<<<dim3(640, 2), 256, 104448>>>(ent, bias, out);
}